// round 1
// baseline (speedup 1.0000x reference)
#include <cuda_runtime.h>
#include <cstdint>

// LocallyConnected2d: B=16, C=32, H=W=64, K=3, pad=1, stride=1
// in_feat = 288, out_ch = 64, L = 4096
// out[b, o, l] = sum_i patch[b, l, i] * weight[l, i, o] + bias[l, o]
// patch feature index i = c*9 + ki*3 + kj, sampling x[b, c, oh-1+ki, ow-1+kj] (0 if OOB)

#define BATCH   16
#define CIN     32
#define INFEAT  288
#define OC      64
#define L_TOT   4096

__global__ __launch_bounds__(64) void lc2d_kernel(
    const float* __restrict__ x,      // (16, 32, 64, 64)
    const float* __restrict__ w,      // (4096, 288, 64)
    const float* __restrict__ bias,   // (4096, 64)
    float* __restrict__ out)          // (16, 64, 4096)
{
    // patch[i][b] : 288 rows x 16 floats, interpreted in compute loop as 8 f32x2 pairs per i
    __shared__ float patch[INFEAT * BATCH];   // 18432 B

    const int l   = blockIdx.x;
    const int oh  = l >> 6;
    const int ow  = l & 63;
    const int tid = threadIdx.x;              // = output channel o

    // ---- Stage the unfolded patch for all 16 batches into SMEM ----
    // t = i*16 + b  -> linear STS (conflict-free); b fastest.
    for (int t = tid; t < INFEAT * BATCH; t += 64) {
        int b  = t & 15;
        int i  = t >> 4;
        int c  = i / 9;
        int r  = i - c * 9;
        int ki = r / 3;
        int kj = r - ki * 3;
        int h  = oh - 1 + ki;
        int wc = ow - 1 + kj;
        float v = 0.0f;
        if ((unsigned)h < 64u && (unsigned)wc < 64u)
            v = x[(((b * CIN + c) << 6) + h << 6) + wc];
        patch[t] = v;
    }
    __syncthreads();

    // ---- Compute: thread owns output channel o = tid, all 16 batches ----
    const float* wl = w + (size_t)l * (INFEAT * OC) + tid;

    unsigned long long acc[8];
#pragma unroll
    for (int j = 0; j < 8; j++) acc[j] = 0ull;   // {0.f, 0.f} packed

    uint32_t sbase = (uint32_t)__cvta_generic_to_shared(patch);

#pragma unroll 4
    for (int i = 0; i < INFEAT; i++) {
        float wv = __ldg(wl + i * OC);           // coalesced 128B per warp
        unsigned long long w2;
        asm("mov.b64 %0, {%1, %1};" : "=l"(w2) : "f"(wv));

        uint32_t a = sbase + (uint32_t)(i * (BATCH * 4));
        unsigned long long p0, p1, p2, p3, p4, p5, p6, p7;
        asm("ld.shared.v2.b64 {%0,%1}, [%2];" : "=l"(p0), "=l"(p1) : "r"(a));
        asm("ld.shared.v2.b64 {%0,%1}, [%2];" : "=l"(p2), "=l"(p3) : "r"(a + 16));
        asm("ld.shared.v2.b64 {%0,%1}, [%2];" : "=l"(p4), "=l"(p5) : "r"(a + 32));
        asm("ld.shared.v2.b64 {%0,%1}, [%2];" : "=l"(p6), "=l"(p7) : "r"(a + 48));

        asm("fma.rn.f32x2 %0, %1, %2, %0;" : "+l"(acc[0]) : "l"(p0), "l"(w2));
        asm("fma.rn.f32x2 %0, %1, %2, %0;" : "+l"(acc[1]) : "l"(p1), "l"(w2));
        asm("fma.rn.f32x2 %0, %1, %2, %0;" : "+l"(acc[2]) : "l"(p2), "l"(w2));
        asm("fma.rn.f32x2 %0, %1, %2, %0;" : "+l"(acc[3]) : "l"(p3), "l"(w2));
        asm("fma.rn.f32x2 %0, %1, %2, %0;" : "+l"(acc[4]) : "l"(p4), "l"(w2));
        asm("fma.rn.f32x2 %0, %1, %2, %0;" : "+l"(acc[5]) : "l"(p5), "l"(w2));
        asm("fma.rn.f32x2 %0, %1, %2, %0;" : "+l"(acc[6]) : "l"(p6), "l"(w2));
        asm("fma.rn.f32x2 %0, %1, %2, %0;" : "+l"(acc[7]) : "l"(p7), "l"(w2));
    }

    // ---- Epilogue: add bias, scatter to (B, OC, L) ----
    float bv = bias[l * OC + tid];
#pragma unroll
    for (int j = 0; j < 8; j++) {
        float lo, hi;
        asm("mov.b64 {%0, %1}, %2;" : "=f"(lo), "=f"(hi) : "l"(acc[j]));
        int b0 = 2 * j;
        int b1 = 2 * j + 1;
        out[((b0 * OC + tid) << 12) + l] = lo + bv;
        out[((b1 * OC + tid) << 12) + l] = hi + bv;
    }
}

extern "C" void kernel_launch(void* const* d_in, const int* in_sizes, int n_in,
                              void* d_out, int out_size) {
    const float* x    = (const float*)d_in[0];
    const float* wgt  = (const float*)d_in[1];
    const float* bias = (const float*)d_in[2];
    float* out        = (float*)d_out;

    lc2d_kernel<<<L_TOT, 64>>>(x, wgt, bias, out);
}

// round 2
// speedup vs baseline: 1.6845x; 1.6845x over previous
#include <cuda_runtime.h>
#include <cstdint>

// LocallyConnected2d: B=16, C=32, H=W=64, K=3, pad=1, stride=1
// out[b, o, l] = sum_i patch[b, l, i] * w[l, i, o] + bias[l, o]
// i = c*9 + ki*3 + kj ; patch samples x[b, c, oh-1+ki, ow-1+kj] (0 OOB)
//
// Layout: 1 CTA (128 thr) = 2x2 output tile = 4 warps, 1 warp per location.
// Lane owns 2 output channels (o = 2*lane, 2*lane+1).
// Shared x tile: [c][r(4)][col(4)][b(16)] for the 4x4 input window union.

#define BATCH   16
#define CIN     32
#define INFEAT  288
#define OC      64
#define TILE_ELEMS (CIN * 4 * 4 * BATCH)   // 8192 floats = 32KB

__global__ __launch_bounds__(128, 6) void lc2d_kernel(
    const float* __restrict__ x,      // (16, 32, 64, 64)
    const float* __restrict__ w,      // (4096, 288, 64)
    const float* __restrict__ bias,   // (4096, 64)
    float* __restrict__ out)          // (16, 64, 64, 64)
{
    __shared__ float tile[TILE_ELEMS];

    const int cta = blockIdx.x;            // 1024 CTAs = 32x32 tiles
    const int th  = cta >> 5;
    const int tw  = cta & 31;
    const int H0  = 2 * th - 1;
    const int W0  = 2 * tw - 1;
    const int tid = threadIdx.x;

    // ---- Stage 4x4 x-window for all channels/batches ----
    for (int e = tid; e < TILE_ELEMS; e += 128) {
        int col = e & 3;
        int r   = (e >> 2) & 3;
        int c   = (e >> 4) & 31;
        int b   = e >> 9;
        int h   = H0 + r;
        int ww  = W0 + col;
        float v = 0.0f;
        if ((unsigned)h < 64u && (unsigned)ww < 64u)
            v = x[(((b * CIN + c) << 6) + h << 6) + ww];
        tile[((c * 4 + r) * 4 + col) * BATCH + b] = v;
    }
    __syncthreads();

    const int wid  = tid >> 5;
    const int lane = tid & 31;
    const int dy   = wid >> 1;
    const int dx   = wid & 1;
    const int l    = ((2 * th + dy) << 6) + (2 * tw + dx);

    const float* wp = w + (size_t)l * (INFEAT * OC) + 2 * lane;
    uint32_t sbase = (uint32_t)__cvta_generic_to_shared(tile)
                   + (uint32_t)((dy * 64 + dx * 16) * 4);

    // acc0[j] : oc=2*lane,   batches (2j, 2j+1) packed f32x2
    // acc1[j] : oc=2*lane+1, batches (2j, 2j+1) packed f32x2
    unsigned long long acc0[8], acc1[8];
#pragma unroll
    for (int j = 0; j < 8; j++) { acc0[j] = 0ull; acc1[j] = 0ull; }

    for (int c = 0; c < CIN; c++) {
#pragma unroll
        for (int k = 0; k < 9; k++) {
            const int ki = k / 3;
            const int kj = k - ki * 3;

            float2 wv = *(const float2*)(wp + (size_t)k * OC);

            unsigned long long w0, w1;
            asm("mov.b64 %0, {%1, %1};" : "=l"(w0) : "f"(wv.x));
            asm("mov.b64 %0, {%1, %1};" : "=l"(w1) : "f"(wv.y));

            uint32_t a = sbase + (uint32_t)(c * 1024)
                       + (uint32_t)((ki * 64 + kj * 16) * 4);
            unsigned long long p0, p1, p2, p3, p4, p5, p6, p7;
            asm("ld.shared.v2.b64 {%0,%1}, [%2];" : "=l"(p0), "=l"(p1) : "r"(a));
            asm("ld.shared.v2.b64 {%0,%1}, [%2];" : "=l"(p2), "=l"(p3) : "r"(a + 16));
            asm("ld.shared.v2.b64 {%0,%1}, [%2];" : "=l"(p4), "=l"(p5) : "r"(a + 32));
            asm("ld.shared.v2.b64 {%0,%1}, [%2];" : "=l"(p6), "=l"(p7) : "r"(a + 48));

            asm("fma.rn.f32x2 %0, %1, %2, %0;" : "+l"(acc0[0]) : "l"(p0), "l"(w0));
            asm("fma.rn.f32x2 %0, %1, %2, %0;" : "+l"(acc0[1]) : "l"(p1), "l"(w0));
            asm("fma.rn.f32x2 %0, %1, %2, %0;" : "+l"(acc0[2]) : "l"(p2), "l"(w0));
            asm("fma.rn.f32x2 %0, %1, %2, %0;" : "+l"(acc0[3]) : "l"(p3), "l"(w0));
            asm("fma.rn.f32x2 %0, %1, %2, %0;" : "+l"(acc0[4]) : "l"(p4), "l"(w0));
            asm("fma.rn.f32x2 %0, %1, %2, %0;" : "+l"(acc0[5]) : "l"(p5), "l"(w0));
            asm("fma.rn.f32x2 %0, %1, %2, %0;" : "+l"(acc0[6]) : "l"(p6), "l"(w0));
            asm("fma.rn.f32x2 %0, %1, %2, %0;" : "+l"(acc0[7]) : "l"(p7), "l"(w0));

            asm("fma.rn.f32x2 %0, %1, %2, %0;" : "+l"(acc1[0]) : "l"(p0), "l"(w1));
            asm("fma.rn.f32x2 %0, %1, %2, %0;" : "+l"(acc1[1]) : "l"(p1), "l"(w1));
            asm("fma.rn.f32x2 %0, %1, %2, %0;" : "+l"(acc1[2]) : "l"(p2), "l"(w1));
            asm("fma.rn.f32x2 %0, %1, %2, %0;" : "+l"(acc1[3]) : "l"(p3), "l"(w1));
            asm("fma.rn.f32x2 %0, %1, %2, %0;" : "+l"(acc1[4]) : "l"(p4), "l"(w1));
            asm("fma.rn.f32x2 %0, %1, %2, %0;" : "+l"(acc1[5]) : "l"(p5), "l"(w1));
            asm("fma.rn.f32x2 %0, %1, %2, %0;" : "+l"(acc1[6]) : "l"(p6), "l"(w1));
            asm("fma.rn.f32x2 %0, %1, %2, %0;" : "+l"(acc1[7]) : "l"(p7), "l"(w1));
        }
        wp += 9 * OC;
    }

    // ---- Epilogue ----
    float2 bv = *(const float2*)(bias + l * OC + 2 * lane);
    const int o0 = 2 * lane;
    float* op = out + o0 * 4096 + l;   // + b*64*4096 per batch

#pragma unroll
    for (int j = 0; j < 8; j++) {
        float lo0, hi0, lo1, hi1;
        asm("mov.b64 {%0, %1}, %2;" : "=f"(lo0), "=f"(hi0) : "l"(acc0[j]));
        asm("mov.b64 {%0, %1}, %2;" : "=f"(lo1), "=f"(hi1) : "l"(acc1[j]));
        int b0 = 2 * j, b1 = 2 * j + 1;
        op[(size_t)(b0 * OC) * 4096]          = lo0 + bv.x;
        op[(size_t)(b1 * OC) * 4096]          = hi0 + bv.x;
        op[(size_t)(b0 * OC) * 4096 + 4096]   = lo1 + bv.y;
        op[(size_t)(b1 * OC) * 4096 + 4096]   = hi1 + bv.y;
    }
}

extern "C" void kernel_launch(void* const* d_in, const int* in_sizes, int n_in,
                              void* d_out, int out_size) {
    const float* x    = (const float*)d_in[0];
    const float* wgt  = (const float*)d_in[1];
    const float* bias = (const float*)d_in[2];
    float* out        = (float*)d_out;

    lc2d_kernel<<<1024, 128>>>(x, wgt, bias, out);
}